// round 9
// baseline (speedup 1.0000x reference)
#include <cuda_runtime.h>
#include <stdint.h>

// Gaussian splatting preprocess.
// R9: R7's constant-bank kernel body (fastest measured: 47.9us) with the
//     constants delivered by ONE tiny init kernel that writes the
//     __constant__ symbol's backing store (instead of 7 graph memcpy nodes).

// Layout: [0:16]=E, [16:32]=I, [32]=fx, [33]=fy, [34]=fw, [35]=fh,
//         [36]=rtile, [37]=clipX, [38]=clipY
__constant__ float cP[40];

__device__ __forceinline__ float decode_scalar(const int* p) {
    int v = __ldg(p);
    if (v >= 0 && v < (1 << 23)) return (float)v;
    return __int_as_float(v);
}

__global__ void init_params_kernel(const float* __restrict__ E,
                                   const float* __restrict__ I,
                                   const int* __restrict__ p_fx,
                                   const int* __restrict__ p_fy,
                                   const int* __restrict__ p_w,
                                   const int* __restrict__ p_h,
                                   const int* __restrict__ p_tile,
                                   float* __restrict__ dst)   // backing store of cP
{
    const int t = threadIdx.x;
    if (t < 16) {
        dst[t]      = __ldg(E + t);
        dst[16 + t] = __ldg(I + t);
    }
    if (t == 0) {
        const float fx   = decode_scalar(p_fx);
        const float fy   = decode_scalar(p_fy);
        const float fw   = decode_scalar(p_w);
        const float fh   = decode_scalar(p_h);
        const float tile = decode_scalar(p_tile);
        dst[32] = fx;
        dst[33] = fy;
        dst[34] = fw;
        dst[35] = fh;
        dst[36] = 1.0f / tile;                   // tile = 16 -> exact
        dst[37] = 1.3f * (fw / (2.0f * fx));     // clipX
        dst[38] = 1.3f * (fh / (2.0f * fy));     // clipY
    }
}

struct PtIn {
    float p0, p1, p2;
    float4 q;
    float s0, s1, s2;
};

__device__ __forceinline__ PtIn load_point(const float* __restrict__ points,
                                           const float* __restrict__ quats,
                                           const float* __restrict__ scales,
                                           int i)
{
    PtIn v;
    v.p0 = __ldg(points + 3*i + 0);
    v.p1 = __ldg(points + 3*i + 1);
    v.p2 = __ldg(points + 3*i + 2);
    v.q  = __ldg(reinterpret_cast<const float4*>(quats) + i);
    v.s0 = __ldg(scales + 3*i + 0);
    v.s1 = __ldg(scales + 3*i + 1);
    v.s2 = __ldg(scales + 3*i + 2);
    return v;
}

__device__ __forceinline__ void process_point(
    const PtIn& in, int i, size_t N,
    const float* __restrict__ colors, const float* __restrict__ opacity,
    int max_tx, int max_ty,
    float* __restrict__ out)
{
    // Store-time loads issued first; the math below hides them.
    const float c0 = __ldg(colors + 3*i + 0);
    const float c1 = __ldg(colors + 3*i + 1);
    const float c2 = __ldg(colors + 3*i + 2);
    const float op = __ldg(opacity + i);

    const float fx    = cP[32];
    const float fy    = cP[33];
    const float fw    = cP[34];
    const float fh    = cP[35];
    const float rtile = cP[36];
    const float clipX = cP[37];
    const float clipY = cP[38];

    // ---- quaternion -> rotation ----
    const float4 q = in.q;
    const float qn = rsqrtf(q.x*q.x + q.y*q.y + q.z*q.z + q.w*q.w);
    const float r  = q.x * qn;
    const float qx = q.y * qn;
    const float qy = q.z * qn;
    const float qz = q.w * qn;

    const float M00 = (1.0f - 2.0f*(qy*qy + qz*qz)) * in.s0;
    const float M01 = (2.0f*(qx*qy - r*qz))         * in.s1;
    const float M02 = (2.0f*(qx*qz + r*qy))         * in.s2;
    const float M10 = (2.0f*(qx*qy + r*qz))         * in.s0;
    const float M11 = (1.0f - 2.0f*(qx*qx + qz*qz)) * in.s1;
    const float M12 = (2.0f*(qy*qz - r*qx))         * in.s2;
    const float M20 = (2.0f*(qx*qz - r*qy))         * in.s0;
    const float M21 = (2.0f*(qy*qz + r*qx))         * in.s1;
    const float M22 = (1.0f - 2.0f*(qx*qx + qy*qy)) * in.s2;

    const float S00 = M00*M00 + M01*M01 + M02*M02;
    const float S01 = M00*M10 + M01*M11 + M02*M12;
    const float S02 = M00*M20 + M01*M21 + M02*M22;
    const float S11 = M10*M10 + M11*M11 + M12*M12;
    const float S12 = M10*M20 + M11*M21 + M12*M22;
    const float S22 = M20*M20 + M21*M21 + M22*M22;

    // pc = [p,1] @ E
    const float pc0 = in.p0*cP[0] + in.p1*cP[4] + in.p2*cP[8]  + cP[12];
    const float pc1 = in.p0*cP[1] + in.p1*cP[5] + in.p2*cP[9]  + cP[13];
    const float pc2 = in.p0*cP[2] + in.p1*cP[6] + in.p2*cP[10] + cP[14];
    const float pc3 = in.p0*cP[3] + in.p1*cP[7] + in.p2*cP[11] + cP[15];

    const float zc    = pc2;
    const bool  zmask = (zc > 0.2f);
    const float zs    = zmask ? zc : 1.0f;
    const float rz    = 1.0f / zs;

    const float xv = fminf(fmaxf(pc0 * rz, -clipX), clipX) * zc;
    const float yv = fminf(fmaxf(pc1 * rz, -clipY), clipY) * zc;

    const float j00 = fx * rz;
    const float j11 = fy * rz;
    const float rz2 = rz * rz;
    const float j02 = -(fx * xv) * rz2;
    const float j12 = -(fy * yv) * rz2;

    const float t00 = cP[0]*j00 + cP[2]*j02;
    const float t01 = cP[4]*j00 + cP[6]*j02;
    const float t02 = cP[8]*j00 + cP[10]*j02;
    const float t10 = cP[1]*j11 + cP[2]*j12;
    const float t11 = cP[5]*j11 + cP[6]*j12;
    const float t12 = cP[9]*j11 + cP[10]*j12;

    const float u0 = S00*t00 + S01*t01 + S02*t02;
    const float u1 = S01*t00 + S11*t01 + S12*t02;
    const float u2 = S02*t00 + S12*t01 + S22*t02;
    const float v0 = S00*t10 + S01*t11 + S02*t12;
    const float v1 = S01*t10 + S11*t11 + S12*t12;
    const float v2 = S02*t10 + S12*t11 + S22*t12;

    const float a = t00*u0 + t01*u1 + t02*u2 + 0.3f;
    const float b = t10*u0 + t11*u1 + t12*u2;
    const float d = t10*v0 + t11*v1 + t12*v2 + 0.3f;

    // ndc = pc @ I
    const float n0 = pc0*cP[16] + pc1*cP[20] + pc2*cP[24] + pc3*cP[28];
    const float n1 = pc0*cP[17] + pc1*cP[21] + pc2*cP[25] + pc3*cP[29];
    const float n2 = pc0*cP[18] + pc1*cP[22] + pc2*cP[26] + pc3*cP[30];
    const float n3 = pc0*cP[19] + pc1*cP[23] + pc2*cP[27] + pc3*cP[31];

    const float rw = 1.0f / (zmask ? n3 : 1.0f);
    const float nx = n0 * rw;
    const float ny = n1 * rw;
    const float nz = n2;

    const bool mask = (nz > 0.2f) && (nx < 1.3f) && (nx > -1.3f)
                                  && (ny < 1.3f) && (ny > -1.3f);

    const float det  = a*d - b*b;
    const float dets = (fabsf(det) < 1e-12f) ? 1e-12f : det;
    const float idet = 1.0f / dets;

    const float mid  = 0.5f * (a + d);
    const float sv   = sqrtf(fmaxf(mid*mid - det, 0.1f));
    const float radius = ceilf(3.0f * sqrtf(fmaxf(mid + sv, 1e-6f)));

    const float px = ((nx + 1.0f) * fw - 1.0f) * 0.5f;
    const float py = ((ny + 1.0f) * fh - 1.0f) * 0.5f;

    int tlx = (int)((px - radius) * rtile);
    int tly = (int)((py - radius) * rtile);
    int brx = (int)((px + radius) * rtile);
    int bry = (int)((py + radius) * rtile);
    tlx = min(max(tlx, 0), max_tx);
    tly = min(max(tly, 0), max_ty);
    brx = min(max(brx, 0), max_tx);
    bry = min(max(bry, 0), max_ty);

    const int span  = max(brx + 1 - tlx, 1) * max(bry + 1 - tly, 1);
    const int tiles = mask ? span : 0;

    float4 f0, f1, f2, f3;
    if (mask) {
        f0 = make_float4(px, py, nz, a);
        f1 = make_float4(b, b, d, d * idet);
        f2 = make_float4(-b * idet, -b * idet, a * idet, radius);
        f3 = make_float4(c0, c1, c2, op);
    } else {
        f0 = make_float4(0.f, 0.f, 0.f, 0.f);
        f1 = f0; f2 = f0; f3 = f0;
    }

    float4* o4 = reinterpret_cast<float4*>(out) + (size_t)i * 4;
    o4[0] = f0; o4[1] = f1; o4[2] = f2; o4[3] = f3;

    out[16*N + i] = (float)tiles;
    out[17*N + i] = (float)tlx;
    out[18*N + i] = (float)tly;
    out[19*N + i] = (float)brx;
    out[20*N + i] = (float)bry;
    out[21*N + i] = mask ? 1.0f : 0.0f;
}

__global__ __launch_bounds__(128, 10)
void gs_pre_kernel(const float* __restrict__ points,
                   const float* __restrict__ quats,
                   const float* __restrict__ scales,
                   const float* __restrict__ colors,
                   const float* __restrict__ opacity,
                   float* __restrict__ out,
                   int n)
{
    const int stride = gridDim.x * blockDim.x;
    int i = blockIdx.x * blockDim.x + threadIdx.x;
    if (i >= n) return;

    const int max_tx = (int)ceilf(cP[34] * cP[36]) - 1;
    const int max_ty = (int)ceilf(cP[35] * cP[36]) - 1;
    const size_t N = (size_t)n;

    PtIn cur = load_point(points, quats, scales, i);

    const int i1 = i + stride;
    const bool has1 = (i1 < n);
    PtIn nxt = load_point(points, quats, scales, has1 ? i1 : i);

    process_point(cur, i, N, colors, opacity, max_tx, max_ty, out);

    if (has1) {
        process_point(nxt, i1, N, colors, opacity, max_tx, max_ty, out);
    }
}

extern "C" void kernel_launch(void* const* d_in, const int* in_sizes, int n_in,
                              void* d_out, int out_size)
{
    const float* points  = (const float*)d_in[0];
    const float* quats   = (const float*)d_in[1];
    const float* scales  = (const float*)d_in[2];
    const float* colors  = (const float*)d_in[3];
    const float* opacity = (const float*)d_in[4];
    const float* E       = (const float*)d_in[5];
    const float* I       = (const float*)d_in[6];
    const int*   p_fx    = (const int*)d_in[7];
    const int*   p_fy    = (const int*)d_in[8];
    const int*   p_w     = (const int*)d_in[9];
    const int*   p_h     = (const int*)d_in[10];
    const int*   p_tile  = (const int*)d_in[11];

    // Backing-store address of the __constant__ symbol (query, not a stream op).
    float* cp_backing = nullptr;
    cudaGetSymbolAddress((void**)&cp_backing, cP);

    const int n = in_sizes[0] / 3;
    float* out = (float*)d_out;

    init_params_kernel<<<1, 32>>>(E, I, p_fx, p_fy, p_w, p_h, p_tile,
                                  cp_backing);

    const int threads = 128;
    const int blocks  = (n + threads * 2 - 1) / (threads * 2);
    gs_pre_kernel<<<blocks, threads>>>(points, quats, scales, colors, opacity,
                                       out, n);
}